// round 1
// baseline (speedup 1.0000x reference)
#include <cuda_runtime.h>
#include <math.h>

// Problem constants (match setup_inputs)
#define N0C 50000
#define E0C 800000
#define N1C 10000
#define E1C 160000
#define FC  128
#define HC  256
#define BC  64

// ---------------- static scratch (no allocations allowed) ----------------
__device__ float g_xw [N0C * HC];   // GEMM result before aggregation (level 0), reused
__device__ float g_x1 [N0C * HC];
__device__ float g_x2 [N0C * HC];
__device__ float g_h  [N0C * HC];
__device__ float g_dinv0[N0C];

__device__ float g_h1cat[N1C * 2 * HC];
__device__ float g_yw [N1C * HC];
__device__ float g_y1 [N1C * HC];
__device__ float g_y2 [N1C * HC];
__device__ float g_hb [N1C * HC];
__device__ float g_dinv1[N1C];

__device__ float g_z [BC * 4 * HC];

// ---------------- small utility kernels ----------------
__global__ void fill_kernel(float* p, int n, float v) {
    int i = blockIdx.x * blockDim.x + threadIdx.x;
    if (i < n) p[i] = v;
}

__global__ void deg_accum_kernel(const int* __restrict__ col,
                                 const float* __restrict__ ew,
                                 float* __restrict__ deg, int E) {
    int e = blockIdx.x * blockDim.x + threadIdx.x;
    if (e < E) atomicAdd(&deg[col[e]], ew[e]);
}

__global__ void finalize_dinv_kernel(float* deg, int n) {
    int i = blockIdx.x * blockDim.x + threadIdx.x;
    if (i < n) {
        float d = deg[i];
        deg[i] = (d > 0.f) ? rsqrtf(d) : 0.f;
    }
}

// out[i,f] = bias[f] + dinv[i]^2 * xw[i,f]   (self-loop term + bias)
__global__ void self_init_kernel(float* __restrict__ out,
                                 const float* __restrict__ xw,
                                 const float* __restrict__ dinv,
                                 const float* __restrict__ bias,
                                 int M, int F) {
    int i = blockIdx.x * blockDim.x + threadIdx.x;
    if (i >= M * F) return;
    int m = i / F;
    int f = i - m * F;
    float di = dinv[m];
    out[i] = bias[f] + di * di * xw[i];
}

// out[col,f] += (dinv[row]*ew*dinv[col]) * xw[row,f]
__global__ void gcn_scatter_kernel(const float* __restrict__ xw,
                                   const int* __restrict__ row,
                                   const int* __restrict__ col,
                                   const float* __restrict__ ew,
                                   const float* __restrict__ dinv,
                                   float* __restrict__ out,
                                   int E, int F, int edgesPerBlock) {
    int f = threadIdx.x;  // 0..F-1 (F==256)
    int e0 = blockIdx.x * edgesPerBlock;
    int e1 = e0 + edgesPerBlock;
    if (e1 > E) e1 = E;
    for (int e = e0; e < e1; e++) {
        int r = row[e], c = col[e];
        float coef = dinv[r] * ew[e] * dinv[c];
        atomicAdd(&out[c * F + f], coef * xw[r * F + f]);
    }
}

// ---------------- tiled SGEMM: C = act( [A1|A2] @ W + bias ) ----------------
// A1: M x K1 (row-major). A2: M x (K-K1). W: K x N (row-major).
// reluIn applies relu to A loads; reluOut to C writes. bias may be NULL.
#define BM 64
#define BN 64
#define BKK 16
__global__ void gemm_kernel(const float* __restrict__ A1,
                            const float* __restrict__ A2,
                            int K1, int K,
                            const float* __restrict__ W,
                            const float* __restrict__ bias,
                            float* __restrict__ C,
                            int M, int N,
                            int reluIn, int reluOut) {
    __shared__ float As[BKK][BM + 1];
    __shared__ float Ws[BKK][BN];
    int bm = blockIdx.y * BM;
    int bn = blockIdx.x * BN;
    int tid = threadIdx.x;          // 0..255
    int tx = tid & 15;              // N direction
    int ty = tid >> 4;              // M direction
    int K2 = K - K1;

    float acc[4][4];
#pragma unroll
    for (int i = 0; i < 4; i++)
#pragma unroll
        for (int j = 0; j < 4; j++) acc[i][j] = 0.f;

    for (int k0 = 0; k0 < K; k0 += BKK) {
        // load A tile (BM x BKK): idx -> m = idx/16, k = idx%16
#pragma unroll
        for (int i = 0; i < 4; i++) {
            int idx = tid + i * 256;
            int m = idx >> 4, k = idx & 15;
            int gm = bm + m, gk = k0 + k;
            float v = 0.f;
            if (gm < M) {
                v = (gk < K1) ? A1[gm * K1 + gk] : A2[gm * K2 + (gk - K1)];
            }
            if (reluIn) v = fmaxf(v, 0.f);
            As[k][m] = v;
        }
        // load W tile (BKK x BN): idx -> k = idx/64, n = idx%64
#pragma unroll
        for (int i = 0; i < 4; i++) {
            int idx = tid + i * 256;
            int k = idx >> 6, n = idx & 63;
            Ws[k][n] = W[(k0 + k) * N + bn + n];
        }
        __syncthreads();
#pragma unroll
        for (int k = 0; k < BKK; k++) {
            float a[4], w[4];
#pragma unroll
            for (int i = 0; i < 4; i++) a[i] = As[k][ty * 4 + i];
#pragma unroll
            for (int j = 0; j < 4; j++) w[j] = Ws[k][tx * 4 + j];
#pragma unroll
            for (int i = 0; i < 4; i++)
#pragma unroll
                for (int j = 0; j < 4; j++) acc[i][j] += a[i] * w[j];
        }
        __syncthreads();
    }
#pragma unroll
    for (int i = 0; i < 4; i++) {
        int gm = bm + ty * 4 + i;
        if (gm >= M) continue;
#pragma unroll
        for (int j = 0; j < 4; j++) {
            int gn = bn + tx * 4 + j;
            float v = acc[i][j];
            if (bias) v += bias[gn];
            if (reluOut) v = fmaxf(v, 0.f);
            C[gm * N + gn] = v;
        }
    }
}

// ---------------- segment pool (sum + max), values assumed >= 0 -----------
// Each block handles a contiguous chunk of rows; thread = one feature.
// Flush partial sum/max on segment-id change (segments are contiguous, so
// each block flushes only a couple of times).
__global__ void segpool_kernel(const float* __restrict__ in,
                               const int* __restrict__ gatherIdx,  // may be NULL
                               const int* __restrict__ seg,
                               int M, int F,
                               float* __restrict__ outSum,
                               float* __restrict__ outMax,
                               int ldOut, int nodesPerBlock) {
    int f = threadIdx.x;
    int n0 = blockIdx.x * nodesPerBlock;
    int n1 = n0 + nodesPerBlock;
    if (n1 > M) n1 = M;
    if (n0 >= n1) return;
    int cur = seg[n0];
    float s = 0.f, mx = 0.f;
    for (int n = n0; n < n1; n++) {
        int sg = seg[n];
        if (sg != cur) {
            atomicAdd(&outSum[cur * ldOut + f], s);
            atomicMax((int*)&outMax[cur * ldOut + f], __float_as_int(mx));
            s = 0.f; mx = 0.f; cur = sg;
        }
        int rowi = gatherIdx ? gatherIdx[n] : n;
        float v = in[rowi * F + f];
        s += v;
        mx = fmaxf(mx, v);
    }
    atomicAdd(&outSum[cur * ldOut + f], s);
    atomicMax((int*)&outMax[cur * ldOut + f], __float_as_int(mx));
}

// ---------------- head: BN -> lin1+relu -> lin2 -> softmax ---------------
__global__ void head_kernel(const float* __restrict__ z,      // B x 1024
                            const float* __restrict__ gamma,
                            const float* __restrict__ beta,
                            const float* __restrict__ mean,
                            const float* __restrict__ var,
                            const float* __restrict__ W1,     // 1024 x 256
                            const float* __restrict__ b1,
                            const float* __restrict__ W2,     // 256 x 10
                            const float* __restrict__ b2,
                            float* __restrict__ out) {        // B x 10
    __shared__ float zn[4 * HC];
    __shared__ float s1[HC];
    __shared__ float logits[16];
    int b = blockIdx.x;
    int t = threadIdx.x;  // 256
    for (int k = t; k < 4 * HC; k += 256) {
        float v = z[b * 4 * HC + k];
        zn[k] = (v - mean[k]) * rsqrtf(var[k] + 1e-5f) * gamma[k] + beta[k];
    }
    __syncthreads();
    float acc = b1[t];
    for (int k = 0; k < 4 * HC; k++) acc += zn[k] * W1[k * HC + t];
    s1[t] = fmaxf(acc, 0.f);
    __syncthreads();
    if (t < 10) {
        float a2 = b2[t];
        for (int k = 0; k < HC; k++) a2 += s1[k] * W2[k * 10 + t];
        logits[t] = a2;
    }
    __syncthreads();
    if (t == 0) {
        float mx = logits[0];
        for (int c = 1; c < 10; c++) mx = fmaxf(mx, logits[c]);
        float e[10], sum = 0.f;
        for (int c = 0; c < 10; c++) { e[c] = expf(logits[c] - mx); sum += e[c]; }
        float inv = 1.f / sum;
        for (int c = 0; c < 10; c++) out[b * 10 + c] = e[c] * inv;
    }
}

// ---------------- orchestration ----------------
static inline int ceil_div(int a, int b) { return (a + b - 1) / b; }

extern "C" void kernel_launch(void* const* d_in, const int* in_sizes, int n_in,
                              void* d_out, int out_size) {
    const float* x      = (const float*)d_in[0];
    const int*   ei0    = (const int*)d_in[1];
    const float* ew0    = (const float*)d_in[2];
    const int*   batch0 = (const int*)d_in[3];
    const int*   cover  = (const int*)d_in[4];
    const int*   ei1    = (const int*)d_in[5];
    const float* ew1    = (const float*)d_in[6];
    const int*   batch1 = (const int*)d_in[7];
    const float* W_in0  = (const float*)d_in[8];
    const float* b_in0  = (const float*)d_in[9];
    const float* W_in1  = (const float*)d_in[10];
    const float* b_in1  = (const float*)d_in[11];
    const float* W_jk_in= (const float*)d_in[12];
    const float* b_jk_in= (const float*)d_in[13];
    const float* W_b0   = (const float*)d_in[14];
    const float* b_b0   = (const float*)d_in[15];
    const float* W_b1   = (const float*)d_in[16];
    const float* b_b1   = (const float*)d_in[17];
    const float* W_jk_b = (const float*)d_in[18];
    const float* b_jk_b = (const float*)d_in[19];
    const float* bn_g   = (const float*)d_in[20];
    const float* bn_b   = (const float*)d_in[21];
    const float* bn_m   = (const float*)d_in[22];
    const float* bn_v   = (const float*)d_in[23];
    const float* W_lin1 = (const float*)d_in[24];
    const float* b_lin1 = (const float*)d_in[25];
    const float* W_lin2 = (const float*)d_in[26];
    const float* b_lin2 = (const float*)d_in[27];
    float* out = (float*)d_out;

    const int N0 = in_sizes[3];
    const int E0 = in_sizes[2];
    const int N1 = in_sizes[7];
    const int E1 = in_sizes[6];
    const int H = HC;

    const int* row0 = ei0;
    const int* col0 = ei0 + E0;
    const int* nodeC = cover;
    const int* clusC = cover + N0;
    const int* row1 = ei1;
    const int* col1 = ei1 + E1;

    // resolve device symbols
    float *xw, *x1, *x2, *h, *dinv0, *h1cat, *yw, *y1, *y2, *hb, *dinv1, *z;
    cudaGetSymbolAddress((void**)&xw, g_xw);
    cudaGetSymbolAddress((void**)&x1, g_x1);
    cudaGetSymbolAddress((void**)&x2, g_x2);
    cudaGetSymbolAddress((void**)&h,  g_h);
    cudaGetSymbolAddress((void**)&dinv0, g_dinv0);
    cudaGetSymbolAddress((void**)&h1cat, g_h1cat);
    cudaGetSymbolAddress((void**)&yw, g_yw);
    cudaGetSymbolAddress((void**)&y1, g_y1);
    cudaGetSymbolAddress((void**)&y2, g_y2);
    cudaGetSymbolAddress((void**)&hb, g_hb);
    cudaGetSymbolAddress((void**)&dinv1, g_dinv1);
    cudaGetSymbolAddress((void**)&z,  g_z);

    // ---- degrees / dinv ----
    fill_kernel<<<ceil_div(N0, 256), 256>>>(dinv0, N0, 1.f);
    deg_accum_kernel<<<ceil_div(E0, 256), 256>>>(col0, ew0, dinv0, E0);
    finalize_dinv_kernel<<<ceil_div(N0, 256), 256>>>(dinv0, N0);
    fill_kernel<<<ceil_div(N1, 256), 256>>>(dinv1, N1, 1.f);
    deg_accum_kernel<<<ceil_div(E1, 256), 256>>>(col1, ew1, dinv1, E1);
    finalize_dinv_kernel<<<ceil_div(N1, 256), 256>>>(dinv1, N1);

    dim3 gemmBlk(256);
    dim3 g0(H / BN, ceil_div(N0, BM));
    dim3 g1(H / BN, ceil_div(N1, BM));

    // ---- level 0: GCN 1 ----
    gemm_kernel<<<g0, gemmBlk>>>(x, x, FC, FC, W_in0, NULL, xw, N0, H, 0, 0);
    self_init_kernel<<<ceil_div(N0 * H, 256), 256>>>(x1, xw, dinv0, b_in0, N0, H);
    gcn_scatter_kernel<<<ceil_div(E0, 8), 256>>>(xw, row0, col0, ew0, dinv0, x1, E0, H, 8);
    // x1 holds pre-relu; relu fused into downstream reads (reluIn=1)

    // ---- level 0: GCN 2 ----
    gemm_kernel<<<g0, gemmBlk>>>(x1, x1, H, H, W_in1, NULL, xw, N0, H, 1, 0);
    self_init_kernel<<<ceil_div(N0 * H, 256), 256>>>(x2, xw, dinv0, b_in1, N0, H);
    gcn_scatter_kernel<<<ceil_div(E0, 8), 256>>>(xw, row0, col0, ew0, dinv0, x2, E0, H, 8);

    // ---- level 0: JK cat + linear + relu ----
    gemm_kernel<<<g0, gemmBlk>>>(x1, x2, H, 2 * H, W_jk_in, b_jk_in, h, N0, H, 1, 1);

    // ---- pools ----
    fill_kernel<<<ceil_div(BC * 4 * H, 256), 256>>>(z, BC * 4 * H, 0.f);
    fill_kernel<<<ceil_div(N1 * 2 * H, 256), 256>>>(h1cat, N1 * 2 * H, 0.f);
    segpool_kernel<<<ceil_div(N0, 128), 256>>>(h, NULL, batch0, N0, H,
                                               z + 0, z + H, 4 * H, 128);
    segpool_kernel<<<ceil_div(N0, 128), 256>>>(h, nodeC, clusC, N0, H,
                                               h1cat + 0, h1cat + H, 2 * H, 128);

    // ---- level 1: GCN 1 ----
    gemm_kernel<<<g1, gemmBlk>>>(h1cat, h1cat, 2 * H, 2 * H, W_b0, NULL, yw, N1, H, 0, 0);
    self_init_kernel<<<ceil_div(N1 * H, 256), 256>>>(y1, yw, dinv1, b_b0, N1, H);
    gcn_scatter_kernel<<<ceil_div(E1, 8), 256>>>(yw, row1, col1, ew1, dinv1, y1, E1, H, 8);

    // ---- level 1: GCN 2 ----
    gemm_kernel<<<g1, gemmBlk>>>(y1, y1, H, H, W_b1, NULL, yw, N1, H, 1, 0);
    self_init_kernel<<<ceil_div(N1 * H, 256), 256>>>(y2, yw, dinv1, b_b1, N1, H);
    gcn_scatter_kernel<<<ceil_div(E1, 8), 256>>>(yw, row1, col1, ew1, dinv1, y2, E1, H, 8);

    // ---- level 1: JK ----
    gemm_kernel<<<g1, gemmBlk>>>(y1, y2, H, 2 * H, W_jk_b, b_jk_b, hb, N1, H, 1, 1);

    // ---- level-1 batch pool ----
    segpool_kernel<<<ceil_div(N1, 128), 256>>>(hb, NULL, batch1, N1, H,
                                               z + 2 * H, z + 3 * H, 4 * H, 128);

    // ---- head ----
    head_kernel<<<BC, 256>>>(z, bn_g, bn_b, bn_m, bn_v,
                             W_lin1, b_lin1, W_lin2, b_lin2, out);
}